// round 17
// baseline (speedup 1.0000x reference)
#include <cuda_runtime.h>
#include <cuda_fp16.h>
#include <cstdint>

typedef unsigned int u32;

#define Nq 8192
#define Mq 8192
#define Dq 64
#define TNr 64
#define NCHUNK 64

#define SH 36    // fp16 tile row stride in u32: conflict-free frag patterns
#define ST 68    // fp16 R^T row stride in u32
#define SR 68    // fp32 staging row stride

#define C1F (1.0f/(128.0f*0.69314718055994531f))
#define C2F (2.0f*C1F)

// SMEM u32 offsets  (total ~83KB -> 2 CTAs/SM)
#define OFF_PH   0                          // 64 x SH
#define OFF_RH   (OFF_PH + 64*SH)           // 2 buffers x 128 x SH
#define OFF_RT   (OFF_RH + 2*128*SH)        // 2 buffers x 64 x ST (also num staging later)
#define OFF_SQP  (OFF_RT + 2*64*ST)         // 64
#define OFF_SQR  (OFF_SQP + 64)             // 2 x 128
#define OFF_DEN  (OFF_SQR + 256)            // 2 x 64
#define SMEM_F   (OFF_DEN + 128)

__device__ u32   g_Ph[2 * Nq * 32];
__device__ u32   g_Rh[2 * Mq * 32];
__device__ float g_sqp[2 * Nq];
__device__ float g_sqr[2 * Mq];
__device__ u32   g_Rt[2 * 64 * 4096];

__device__ __forceinline__ void mma_f16(float c[4], u32 a0, u32 a1, u32 a2, u32 a3,
                                        u32 b0, u32 b1)
{
    asm volatile(
        "mma.sync.aligned.m16n8k16.row.col.f32.f16.f16.f32 "
        "{%0,%1,%2,%3}, {%4,%5,%6,%7}, {%8,%9}, {%0,%1,%2,%3};"
        : "+f"(c[0]), "+f"(c[1]), "+f"(c[2]), "+f"(c[3])
        : "r"(a0), "r"(a1), "r"(a2), "r"(a3), "r"(b0), "r"(b1));
}
__device__ __forceinline__ float ex2(float x){
    float r; asm("ex2.approx.ftz.f32 %0, %1;" : "=f"(r) : "f"(x)); return r;
}
__device__ __forceinline__ float rcpf(float x){
    float r; asm("rcp.approx.ftz.f32 %0, %1;" : "=f"(r) : "f"(x)); return r;
}
__device__ __forceinline__ u32 pkhf(float lo, float hi){
    u32 d; asm("cvt.rn.f16x2.f32 %0, %1, %2;" : "=r"(d) : "f"(hi), "f"(lo));
    return d;
}
__device__ __forceinline__ void cpasync16(u32 dst, const void* src){
    asm volatile("cp.async.cg.shared.global [%0], [%1], 16;" :: "r"(dst), "l"(src));
}

__global__ void prep_kernel(const float* __restrict__ P, const float* __restrict__ R)
{
    int warp = (blockIdx.x * blockDim.x + threadIdx.x) >> 5;
    int lane = threadIdx.x & 31;
    const float* src; u32* dst; float* nrm;
    if (warp < 2 * Nq){
        src = P + (size_t)warp * Dq; dst = g_Ph + (size_t)warp * 32; nrm = g_sqp + warp;
    } else {
        int row = warp - 2 * Nq;
        src = R + (size_t)row * Dq; dst = g_Rh + (size_t)row * 32; nrm = g_sqr + row;
    }
    float2 v = ((const float2*)src)[lane];
    float x = __half2float(__float2half_rn(v.x));
    float y = __half2float(__float2half_rn(v.y));
    dst[lane] = pkhf(x, y);
    float s = x * x + y * y;
    #pragma unroll
    for (int o = 16; o; o >>= 1) s += __shfl_xor_sync(0xffffffffu, s, o);
    if (lane == 0) nrm[0] = s * C1F;
}

__global__ void transpose_kernel(const float* __restrict__ Rsrc)
{
    __shared__ u32 st[64 * 68];
    const int chunk = blockIdx.x;
    const int t = threadIdx.x;
    const float4* src = (const float4*)(Rsrc + (size_t)chunk * 128 * Dq);
    __half* bp = (__half*)st;
    #pragma unroll
    for (int it = 0; it < 8; it++){
        int idx = t + (it << 8);
        int m = idx >> 4, j4 = idx & 15;
        float4 v = src[idx];
        bp[(4*j4 + 0) * 136 + m] = __float2half_rn(v.x);
        bp[(4*j4 + 1) * 136 + m] = __float2half_rn(v.y);
        bp[(4*j4 + 2) * 136 + m] = __float2half_rn(v.z);
        bp[(4*j4 + 3) * 136 + m] = __float2half_rn(v.w);
    }
    __syncthreads();
    u32* dst = g_Rt + (size_t)chunk * 4096;
    #pragma unroll
    for (int it = 0; it < 4; it++){
        int idx = t + (it << 8);
        int j = idx >> 4, s = idx & 15;
        uint4 v = *(const uint4*)&st[j * 68 + s * 4];
        *(uint4*)&dst[j * 64 + s * 4] = v;
    }
}

// cp.async one chunk's Rh + Rt + sqr
__device__ __forceinline__ void load_chunk(u32* RhD, u32* RtD, float* sqD,
                                           const u32* rhg, const u32* rtg,
                                           const float* sqg, int t)
{
    #pragma unroll
    for (int it = 0; it < 4; it++){
        int idx = t + (it << 8);
        int r = idx >> 3, q = idx & 7;
        cpasync16((u32)__cvta_generic_to_shared(&RhD[r * SH + q * 4]), rhg + r * 32 + q * 4);
    }
    #pragma unroll
    for (int it = 0; it < 4; it++){
        int idx = t + (it << 8);
        int j = idx >> 4, s2 = idx & 15;
        cpasync16((u32)__cvta_generic_to_shared(&RtD[j * ST + s2 * 4]), rtg + j * 64 + s2 * 4);
    }
    if (t < 32) cpasync16((u32)__cvta_generic_to_shared(&sqD[t * 4]), sqg + t * 4);
}

__global__ void __launch_bounds__(256, 2) ms_kernel(float* __restrict__ out)
{
    extern __shared__ float sm[];
    u32*   Ph   = (u32*)sm + OFF_PH;
    u32*   Rh0  = (u32*)sm + OFF_RH;
    u32*   Rt0  = (u32*)sm + OFF_RT;
    float* numb = (float*)((u32*)sm + OFF_RT);   // union: reused after main loop
    float* sqp  = sm + OFF_SQP;
    float* sqr0 = sm + OFF_SQR;
    float* denp = sm + OFF_DEN;

    const int t = threadIdx.x;
    const int w = t >> 5, l = t & 31;
    const int gid = l >> 2, tig = l & 3;
    const int b = blockIdx.y;
    const int n0 = blockIdx.x * TNr;
    const u32* Phg = g_Ph + ((size_t)b * Nq + n0) * 32;
    const u32* Rhg = g_Rh + (size_t)b * Mq * 32;
    const u32* Rtg = g_Rt + (size_t)b * 64 * 4096;
    const float* sqpg = g_sqp + b * Nq + n0;
    const float* sqrg = g_sqr + b * Mq;

    // Warp grid 4m x 2half: 16 rows per warp, half = GEMM1 n-slice = GEMM2 k-half
    const int wm = (w & 3) * 16;
    const int half = w >> 2;
    const int wn1 = half * 64;

    // ---- Prologue: group0 = Ph + sqp + chunk0 ; group1 = chunk1 ----
    {
        #pragma unroll
        for (int it = 0; it < 2; it++){
            int idx = t + (it << 8);            // 0..511
            int r = idx >> 3, q = idx & 7;
            cpasync16((u32)__cvta_generic_to_shared(&Ph[r * SH + q * 4]), Phg + r * 32 + q * 4);
        }
        if (t < 16) cpasync16((u32)__cvta_generic_to_shared(&sqp[t * 4]), sqpg + t * 4);
        load_chunk(Rh0, Rt0, sqr0, Rhg, Rtg, sqrg, t);
        asm volatile("cp.async.commit_group;");
        load_chunk(Rh0 + 128*SH, Rt0 + 64*ST, sqr0 + 128,
                   Rhg + 128*32, Rtg + 4096, sqrg + 128, t);
        asm volatile("cp.async.commit_group;");
    }

    float nacc[8][4];
    float denacc[4];
    #pragma unroll
    for (int j = 0; j < 8; j++)
        #pragma unroll
        for (int q = 0; q < 4; q++) nacc[j][q] = 0.f;
    #pragma unroll
    for (int q = 0; q < 4; q++) denacc[q] = 0.f;
    const u32 ONE2 = 0x3C003C00u;

    for (int i = 0; i < NCHUNK; i++){
        const int p = i & 1;
        const u32* Rh = Rh0 + p * 128 * SH;
        const u32* Rt = Rt0 + p * 64 * ST;
        const float* sqr = sqr0 + p * 128;

        asm volatile("cp.async.wait_group 1;" ::: "memory");
        __syncthreads();

        // ---- GEMM1 (fp16): S = P . R^T  (warp tile 16 x 64) ----
        float sa[8][4];
        #pragma unroll
        for (int nt = 0; nt < 8; nt++)
            #pragma unroll
            for (int q = 0; q < 4; q++) sa[nt][q] = 0.f;

        #pragma unroll
        for (int ks = 0; ks < 4; ks++){
            const u32* pa = &Ph[(wm + gid) * SH + ks*8 + tig];
            u32 a0 = pa[0], a1 = pa[8*SH], a2 = pa[4], a3 = pa[8*SH + 4];
            #pragma unroll
            for (int nt = 0; nt < 8; nt++){
                const u32* pb = &Rh[(wn1 + 8*nt + gid) * SH + ks*8 + tig];
                mma_f16(sa[nt], a0, a1, a2, a3, pb[0], pb[4]);
            }
        }

        // ---- Prefetch chunk i+1 into the slot freed... (2-stage: i+1 already in
        //      flight; issue i+2's would need slot p -> instead prefetch i+1-style:
        //      issue chunk i+2 into slot p AFTER this chunk's reads are done is not
        //      possible with 2 buffers until GEMM2 finishes; so prefetch goes last.)

        // ---- Epilogue in registers + GEMM2 (fp16): same chunk ----
        u32 kc[4][4];
        #pragma unroll
        for (int kt = 0; kt < 4; kt++){
            const int r0 = wm + gid;
            const float spa0 = sqp[r0];
            const float spa1 = sqp[r0 + 8];
            #pragma unroll
            for (int h = 0; h < 2; h++){
                int nt = 2*kt + h;
                int c0 = wn1 + 8*nt + 2*tig;
                float2 q = *(const float2*)&sqr[c0];
                float e0 = ex2(fmaf(C2F, sa[nt][0], -spa0 - q.x));
                float e1 = ex2(fmaf(C2F, sa[nt][1], -spa0 - q.y));
                float e2 = ex2(fmaf(C2F, sa[nt][2], -spa1 - q.x));
                float e3 = ex2(fmaf(C2F, sa[nt][3], -spa1 - q.y));
                kc[kt][2*h + 0] = pkhf(e0, e1);
                kc[kt][2*h + 1] = pkhf(e2, e3);
            }
            const int koff = (wn1 >> 1) + 8*kt + tig;
            #pragma unroll
            for (int jt = 0; jt < 8; jt++){
                const u32* pb = &Rt[(8*jt + gid) * ST + koff];
                mma_f16(nacc[jt], kc[kt][0], kc[kt][1], kc[kt][2], kc[kt][3],
                        pb[0], pb[4]);
            }
            mma_f16(denacc, kc[kt][0], kc[kt][1], kc[kt][2], kc[kt][3], ONE2, ONE2);
        }

        // ---- Now slot p is fully consumed: prefetch chunk i+2 into it ----
        __syncthreads();
        if (i + 2 < NCHUNK){
            load_chunk(Rh0 + p * 128 * SH, Rt0 + p * 64 * ST, sqr0 + p * 128,
                       Rhg + (size_t)(i + 2) * 128 * 32,
                       Rtg + (size_t)(i + 2) * 4096,
                       sqrg + (size_t)(i + 2) * 128, t);
        }
        asm volatile("cp.async.commit_group;");
    }

    // ---- Denominator partials ----
    if (tig == 0){
        denp[half * 64 + wm + gid]     = denacc[0];
        denp[half * 64 + wm + 8 + gid] = denacc[2];
    }

    // ---- Combine the two k-half numerator partials (numb unions dead Rt slot 0) ----
    __syncthreads();
    if (half == 0){
        int r0 = wm + gid;
        #pragma unroll
        for (int jt = 0; jt < 8; jt++){
            int c0 = 8*jt + 2*tig;
            *(float2*)&numb[r0 * SR + c0]       = make_float2(nacc[jt][0], nacc[jt][1]);
            *(float2*)&numb[(r0 + 8) * SR + c0] = make_float2(nacc[jt][2], nacc[jt][3]);
        }
    }
    __syncthreads();
    if (half == 1){
        int r0 = wm + gid;
        #pragma unroll
        for (int jt = 0; jt < 8; jt++){
            int c0 = 8*jt + 2*tig;
            float2 u0 = *(const float2*)&numb[r0 * SR + c0];
            float2 u1 = *(const float2*)&numb[(r0 + 8) * SR + c0];
            u0.x += nacc[jt][0]; u0.y += nacc[jt][1];
            u1.x += nacc[jt][2]; u1.y += nacc[jt][3];
            *(float2*)&numb[r0 * SR + c0]       = u0;
            *(float2*)&numb[(r0 + 8) * SR + c0] = u1;
        }
    }
    __syncthreads();

    // ---- Coalesced writeback: out = num / den ----
    float4* Ob = (float4*)(out + ((size_t)b * Nq + n0) * Dq);
    #pragma unroll
    for (int it = 0; it < 4; it++){
        int idx = t + (it << 8);                // 0..1023 float4s
        int r = idx >> 4, c4 = idx & 15;
        float4 v = *(const float4*)&numb[r * SR + c4 * 4];
        float inv = rcpf(denp[r] + denp[64 + r]);
        v.x *= inv; v.y *= inv; v.z *= inv; v.w *= inv;
        Ob[idx] = v;
    }
}

extern "C" void kernel_launch(void* const* d_in, const int* in_sizes, int n_in,
                              void* d_out, int out_size)
{
    const float* points = (const float*)d_in[0];
    const float* refp   = (const float*)d_in[1];
    float* out          = (float*)d_out;

    {
        int warps = 2 * Nq + 2 * Mq;
        prep_kernel<<<warps / 8, 256>>>(points, refp);
    }
    transpose_kernel<<<128, 256>>>(refp);

    const int smem_bytes = SMEM_F * (int)sizeof(float);
    static int attr_set = 0;
    if (!attr_set){
        cudaFuncSetAttribute(ms_kernel,
                             cudaFuncAttributeMaxDynamicSharedMemorySize, smem_bytes);
        attr_set = 1;
    }
    dim3 grid(Nq / TNr, 2);
    ms_kernel<<<grid, 256, smem_bytes>>>(out);
}